// round 14
// baseline (speedup 1.0000x reference)
#include <cuda_runtime.h>
#include <cstdint>

#define NBOX      5000
#define NCLS      81
#define MAXI      100
#define CLSMAX    128
#define GRID      80           // one block per class; all co-resident
#define TPB       512          // 16 warps -> 1280 warps >= 1250 ROI-quads
#define KEPTMAX   (80 * MAXI)
#define CANDCAP   512
#define MIN_CONF  0.7f
#define NMS_THR   0.3f

typedef unsigned long long ull;

// Persistent scratch. Counters zero at load; re-zeroed each launch by the
// phase-3 block -> deterministic across graph replays.
__device__ ull    g_clsKeys[NCLS * CLSMAX];
__device__ float4 g_clsBox[NCLS * CLSMAX];
__device__ int    g_clsCnt[NCLS];
__device__ ull    g_kKey[KEPTMAX];          // compact kept list
__device__ float4 g_kBox[KEPTMAX];
__device__ int    g_kCls[KEPTMAX];
__device__ int    g_keptTotal;
__device__ int    g_hist[1024];
__device__ int    g_bar1;
__device__ int    g_bar2;

__device__ __forceinline__ int score_bin(float s) {
    int b = (int)((s - MIN_CONF) * (1024.0f / 0.3f));
    return min(1023, max(0, b));
}

struct P2 {                        // phase-2 workspace: ONE class per block
    ull    keys[CLSMAX];
    ull    skey[CLSMAX];
    float4 box[CLSMAX];
    float  ar[CLSMAX];
    uint4  mask[CLSMAX];           // 128-bit overlap mask per row (lower-tri)
};
struct P3 {                        // phase-3 workspace
    int    hist[1024];
    ull    ckey[CANDCAP];
    float4 cbox[CANDCAP];
    int    ccls[CANDCAP];
};
union SmemU { P2 p2; P3 p3; };

__global__ void __launch_bounds__(TPB)
k_all(const float* __restrict__ rois,
      const float* __restrict__ probs,
      const float* __restrict__ deltas,
      const float* __restrict__ window,
      float* __restrict__ out)
{
    const int tid  = threadIdx.x;
    const int warp = tid >> 5;
    const int lane = tid & 31;
    const int gw   = blockIdx.x * (TPB / 32) + warp;   // 0..1279

    __shared__ SmemU u;
    __shared__ int s_flag, s_ccnt, s_bstar, s_base;
    __shared__ ull s_k0, s_k1;

    // ============ Phase 1: refine — one ROI-quad per warp ==================
    const int r0 = 4 * gw;
    if (r0 < NBOX) {
        const float4 w4 = ((const float4*)window)[0];  // (wy1,wx1,wy2,wx2)

        float4 roi;
        if (lane < 4) roi = ((const float4*)rois)[r0 + lane];

        // All 12 probs loads issued upfront (independent -> high MLP).
        ull key[4];
        #pragma unroll
        for (int q = 0; q < 4; q++) {
            const float* p = probs + (size_t)(r0 + q) * NCLS;
            float v0 = p[lane];
            float v1 = p[lane + 32];
            float v2 = (lane < NCLS - 64) ? p[lane + 64] : -1.0f;
            ull k0 = ((ull)__float_as_uint(v0) << 32) | (0xFFFFFFFFu - (unsigned)lane);
            ull k1 = ((ull)__float_as_uint(v1) << 32) | (0xFFFFFFFFu - (unsigned)(lane + 32));
            ull k2 = (lane < NCLS - 64)
                   ? (((ull)__float_as_uint(v2) << 32) | (0xFFFFFFFFu - (unsigned)(lane + 64)))
                   : 0ULL;
            key[q] = max(k0, max(k1, k2));     // max prob, tie -> lower class
        }
        #pragma unroll
        for (int off = 16; off; off >>= 1) {
            #pragma unroll
            for (int q = 0; q < 4; q++) {
                ull o = __shfl_xor_sync(0xffffffffu, key[q], off);
                key[q] = max(key[q], o);
            }
        }

        if (lane < 4) {
            ull  k  = key[lane];
            float bp = __uint_as_float((unsigned)(k >> 32));
            int   bi = (int)(0xFFFFFFFFu - (unsigned)(k & 0xFFFFFFFFu));
            if (bi > 0 && bp >= MIN_CONF) {
                int r = r0 + lane;
                float4 d4 = *(const float4*)(deltas + ((size_t)r * NCLS + bi) * 4);
                float h  = roi.z - roi.x;
                float wd = roi.w - roi.y;
                float cy = roi.x + 0.5f * h;
                float cx = roi.y + 0.5f * wd;
                cy += (d4.x * 0.1f) * h;
                cx += (d4.y * 0.1f) * wd;
                h  *= expf(d4.z * 0.2f);
                wd *= expf(d4.w * 0.2f);
                float y1 = cy - 0.5f * h;
                float x1 = cx - 0.5f * wd;
                float y2 = y1 + h;
                float x2 = x1 + wd;
                y1 = fminf(fmaxf(y1, w4.x), w4.z);
                x1 = fminf(fmaxf(x1, w4.y), w4.w);
                y2 = fminf(fmaxf(y2, w4.x), w4.z);
                x2 = fminf(fmaxf(x2, w4.y), w4.w);

                ull okey = ((ull)__float_as_uint(bp) << 32) |
                           (unsigned)(0xFFFFFFFFu - (unsigned)r);
                int pos = atomicAdd(&g_clsCnt[bi], 1);
                if (pos < CLSMAX) {
                    g_clsKeys[bi * CLSMAX + pos] = okey;
                    g_clsBox[bi * CLSMAX + pos]  = make_float4(y1, x1, y2, x2);
                }
            }
        }
    }

    // ---- global barrier 1: all 80 blocks arrive, all wait ----
    __syncthreads();
    if (tid == 0) {
        __threadfence();
        atomicAdd(&g_bar1, 1);
        while (*((volatile int*)&g_bar1) < GRID) { }
    }
    __syncthreads();
    __threadfence();

    // ============ Phase 2: NMS — one block per class ========================
    const int cseg = blockIdx.x;           // 0..79
    const int c    = cseg + 1;             // class 1..80
    int cnt = min(g_clsCnt[c], CLSMAX);

    if (cnt > 0) {
        ull    myKey = 0;
        float4 myBox;
        if (tid < cnt) {
            myKey = g_clsKeys[c * CLSMAX + tid];
            myBox = g_clsBox[c * CLSMAX + tid];
            u.p2.keys[tid] = myKey;
        }
        __syncthreads();

        // Block rank-sort (descending): rank = #{keys greater}; keys unique.
        if (tid < cnt) {
            int rk = 0;
            for (int j = 0; j < cnt; j++) rk += (u.p2.keys[j] > myKey);
            u.p2.skey[rk] = myKey;
            u.p2.box[rk]  = myBox;
            u.p2.ar[rk]   = fmaxf(myBox.z - myBox.x, 0.0f) *
                            fmaxf(myBox.w - myBox.y, 0.0f);
        }
        __syncthreads();

        // Overlap mask build: one (row i, 32-wide chunk k) item per thread.
        if (tid < cnt * 4) {
            int i = tid % cnt;
            int k = tid / cnt;                 // 0..3
            float4 bi = u.p2.box[i];
            float  ia = u.p2.ar[i];
            unsigned w = 0u;
            int jend = min(i, (k + 1) * 32);
            for (int j = k * 32; j < jend; j++) {
                float4 bj = u.p2.box[j];
                float yy1 = fmaxf(bi.x, bj.x);
                float xx1 = fmaxf(bi.y, bj.y);
                float yy2 = fminf(bi.z, bj.z);
                float xx2 = fminf(bi.w, bj.w);
                float inter = fmaxf(yy2 - yy1, 0.0f) * fmaxf(xx2 - xx1, 0.0f);
                float uni   = ia + u.p2.ar[j] - inter;
                // iou > THR  <=>  uni>0 && inter > THR*max(uni,1e-12)
                if (uni > 0.0f && inter > NMS_THR * fmaxf(uni, 1e-12f))
                    w |= 1u << (j - k * 32);
            }
            ((unsigned*)&u.p2.mask[i])[k] = w;
        }
        __syncthreads();

        // Serial greedy sweep on WARP 0 ONLY (one instruction stream; the
        // other 15 warps would just replicate it and burn issue slots).
        // Lane 0 publishes kept masks + reserves the compact segment; the
        // atomic's round-trip overlaps the broadcast barrier.
        if (warp == 0) {
            ull kept0 = 0ULL, kept1 = 0ULL;
            int cntK = 0;
            uint4 nxt = u.p2.mask[0];
            for (int i = 0; i < cnt; i++) {
                uint4 cur = nxt;
                if (i + 1 < cnt) nxt = u.p2.mask[i + 1];
                ull lo = (ull)cur.x | ((ull)cur.y << 32);
                ull hi = (ull)cur.z | ((ull)cur.w << 32);
                bool ok = (((lo & kept0) | (hi & kept1)) == 0ULL) && (cntK < MAXI);
                if (ok) {
                    if (i < 64) kept0 |= 1ULL << i;
                    else        kept1 |= 1ULL << (i - 64);
                    cntK++;
                }
            }
            if (lane == 0) {
                s_k0 = kept0;
                s_k1 = kept1;
                s_base = atomicAdd(&g_keptTotal, cntK);
            }
        }
        __syncthreads();

        const ull kept0 = s_k0;
        const ull kept1 = s_k1;
        const int base  = s_base;

        // Emit kept (key, box, cls) at base+rank + fire-and-forget histogram.
        if (tid < cnt) {
            int t = tid;
            bool isKept = (t < 64) ? ((kept0 >> t) & 1ULL)
                                   : ((kept1 >> (t - 64)) & 1ULL);
            if (isKept) {
                int rank;
                if (t < 64) rank = __popcll(kept0 & ((1ULL << t) - 1ULL));
                else        rank = __popcll(kept0) +
                                   __popcll(kept1 & ((1ULL << (t - 64)) - 1ULL));
                ull key = u.p2.skey[t];
                g_kKey[base + rank] = key;
                g_kBox[base + rank] = u.p2.box[t];
                g_kCls[base + rank] = c;
                float sc = __uint_as_float((unsigned)(key >> 32));
                atomicAdd(&g_hist[score_bin(sc)], 1);
            }
        }
    }

    // ---- barrier 2: last-arriving block runs phase 3 (no spin) ----
    __syncthreads();
    if (tid == 0) {
        __threadfence();
        int prev = atomicAdd(&g_bar2, 1);
        s_flag = (prev == GRID - 1);
    }
    __syncthreads();
    if (!s_flag) return;
    __threadfence();

    // ==================== Phase 3: top-100 (last block) =====================
    const int n = *((volatile int*)&g_keptTotal);

    for (int b = tid; b < 1024; b += TPB) {
        u.p3.hist[b] = g_hist[b];
        g_hist[b] = 0;                         // clear for next launch
    }
    if (tid == 0) { s_ccnt = 0; s_bstar = 0; }
    if (tid < MAXI) {
        #pragma unroll
        for (int q = 0; q < 6; q++) out[tid * 6 + q] = 0.0f;
    }
    __syncthreads();

    // Warp 0: suffix-scan 1024 bins; B = largest bin with S(B) >= MAXI.
    if (warp == 0) {
        int base = lane * 32;
        int csum = 0;
        #pragma unroll
        for (int b = 0; b < 32; b++) csum += u.p3.hist[base + b];
        int v = csum;
        #pragma unroll
        for (int off = 1; off < 32; off <<= 1) {
            int t = __shfl_down_sync(0xffffffffu, v, off);
            if (lane + off < 32) v += t;
        }
        int running = v - csum;                // suffix of higher 32-chunks
        for (int b = 31; b >= 0; b--) {
            int S = running + u.p3.hist[base + b];
            if (S >= MAXI && running < MAXI) s_bstar = base + b;
            running = S;
        }
    }
    __syncthreads();
    const int B = s_bstar;

    // Collect candidates with bin >= B from the compact list (coalesced).
    for (int s = tid; s < n; s += TPB) {
        ull key = g_kKey[s];
        float sc = __uint_as_float((unsigned)(key >> 32));
        if (score_bin(sc) >= B) {
            int pos = atomicAdd(&s_ccnt, 1);
            if (pos < CANDCAP) {
                u.p3.ckey[pos] = key;
                u.p3.cbox[pos] = g_kBox[s];    // issued now, consumed post-sync
                u.p3.ccls[pos] = g_kCls[s];
            }
        }
    }
    __syncthreads();
    int k2 = min(s_ccnt, CANDCAP);

    // Rank-select: rank = #{keys greater}; unique keys -> unique ranks.
    for (int t = tid; t < k2; t += TPB) {
        ull key = u.p3.ckey[t];
        int rank = 0;
        for (int j = 0; j < k2; j++) rank += (u.p3.ckey[j] > key);
        if (rank < MAXI) {
            float4 b4 = u.p3.cbox[t];
            out[rank * 6 + 0] = b4.x;
            out[rank * 6 + 1] = b4.y;
            out[rank * 6 + 2] = b4.z;
            out[rank * 6 + 3] = b4.w;
            out[rank * 6 + 4] = (float)u.p3.ccls[t];
            out[rank * 6 + 5] = __uint_as_float((unsigned)(key >> 32));
        }
    }

    // Reset counters for the next (graph-replayed) launch.
    __syncthreads();
    if (tid < NCLS) g_clsCnt[tid] = 0;
    if (tid == 128) g_bar1 = 0;
    if (tid == 129) g_bar2 = 0;
    if (tid == 130) g_keptTotal = 0;
}

extern "C" void kernel_launch(void* const* d_in, const int* in_sizes, int n_in,
                              void* d_out, int out_size)
{
    const float* rois   = (const float*)d_in[0];
    const float* probs  = (const float*)d_in[1];
    const float* deltas = (const float*)d_in[2];
    const float* window = (const float*)d_in[3];
    float* out = (float*)d_out;

    k_all<<<GRID, TPB>>>(rois, probs, deltas, window, out);
}

// round 15
// speedup vs baseline: 1.3159x; 1.3159x over previous
#include <cuda_runtime.h>
#include <cstdint>

#define NBOX      5000
#define NCLS      81
#define MAXI      100
#define CLSMAX    128
#define GRID      80           // one block per class; all co-resident
#define TPB       512          // 16 warps -> 1280 warps >= 1250 ROI-quads
#define KEPTMAX   (80 * MAXI)
#define CANDCAP   512
#define MIN_CONF  0.7f
#define NMS_THR   0.3f

typedef unsigned long long ull;

// Persistent scratch. Counters zero at load; re-zeroed each launch by the
// phase-3 block -> deterministic across graph replays.
__device__ ull    g_clsKeys[NCLS * CLSMAX];
__device__ float4 g_clsBox[NCLS * CLSMAX];
__device__ int    g_clsCnt[NCLS];
__device__ ull    g_kKey[KEPTMAX];          // compact kept list
__device__ float4 g_kBox[KEPTMAX];
__device__ int    g_kCls[KEPTMAX];
__device__ int    g_keptTotal;
__device__ int    g_hist[1024];
__device__ int    g_bar1;
__device__ int    g_bar2;

__device__ __forceinline__ int score_bin(float s) {
    int b = (int)((s - MIN_CONF) * (1024.0f / 0.3f));
    return min(1023, max(0, b));
}

struct P2 {                        // phase-2 workspace: ONE class per block
    ull    keys[CLSMAX];
    ull    skey[CLSMAX];
    float4 box[CLSMAX];
    float  ar[CLSMAX];
    uint4  mask[CLSMAX];           // 128-bit overlap mask per row (lower-tri)
};
struct P3 {                        // phase-3 workspace
    int    hist[1024];
    ull    ckey[CANDCAP];
    float4 cbox[CANDCAP];
    int    ccls[CANDCAP];
};
union SmemU { P2 p2; P3 p3; };

__global__ void __launch_bounds__(TPB)
k_all(const float* __restrict__ rois,
      const float* __restrict__ probs,
      const float* __restrict__ deltas,
      const float* __restrict__ window,
      float* __restrict__ out)
{
    const int tid  = threadIdx.x;
    const int warp = tid >> 5;
    const int lane = tid & 31;
    const int gw   = blockIdx.x * (TPB / 32) + warp;   // 0..1279

    __shared__ SmemU u;
    __shared__ int s_flag, s_ccnt, s_bstar, s_base;

    // ============ Phase 1: refine — one ROI-quad per warp ==================
    const int r0 = 4 * gw;
    if (r0 < NBOX) {
        const float4 w4 = ((const float4*)window)[0];  // (wy1,wx1,wy2,wx2)

        float4 roi;
        if (lane < 4) roi = ((const float4*)rois)[r0 + lane];

        // All 12 probs loads issued upfront (independent -> high MLP).
        ull key[4];
        #pragma unroll
        for (int q = 0; q < 4; q++) {
            const float* p = probs + (size_t)(r0 + q) * NCLS;
            float v0 = p[lane];
            float v1 = p[lane + 32];
            float v2 = (lane < NCLS - 64) ? p[lane + 64] : -1.0f;
            ull k0 = ((ull)__float_as_uint(v0) << 32) | (0xFFFFFFFFu - (unsigned)lane);
            ull k1 = ((ull)__float_as_uint(v1) << 32) | (0xFFFFFFFFu - (unsigned)(lane + 32));
            ull k2 = (lane < NCLS - 64)
                   ? (((ull)__float_as_uint(v2) << 32) | (0xFFFFFFFFu - (unsigned)(lane + 64)))
                   : 0ULL;
            key[q] = max(k0, max(k1, k2));     // max prob, tie -> lower class
        }
        #pragma unroll
        for (int off = 16; off; off >>= 1) {
            #pragma unroll
            for (int q = 0; q < 4; q++) {
                ull o = __shfl_xor_sync(0xffffffffu, key[q], off);
                key[q] = max(key[q], o);
            }
        }

        if (lane < 4) {
            ull  k  = key[lane];
            float bp = __uint_as_float((unsigned)(k >> 32));
            int   bi = (int)(0xFFFFFFFFu - (unsigned)(k & 0xFFFFFFFFu));
            if (bi > 0 && bp >= MIN_CONF) {
                int r = r0 + lane;
                // Issue the slot-reservation atomic FIRST: its round-trip
                // overlaps the (independent) deltas gather + box math.
                int pos = atomicAdd(&g_clsCnt[bi], 1);
                float4 d4 = *(const float4*)(deltas + ((size_t)r * NCLS + bi) * 4);
                float h  = roi.z - roi.x;
                float wd = roi.w - roi.y;
                float cy = roi.x + 0.5f * h;
                float cx = roi.y + 0.5f * wd;
                cy += (d4.x * 0.1f) * h;
                cx += (d4.y * 0.1f) * wd;
                h  *= expf(d4.z * 0.2f);
                wd *= expf(d4.w * 0.2f);
                float y1 = cy - 0.5f * h;
                float x1 = cx - 0.5f * wd;
                float y2 = y1 + h;
                float x2 = x1 + wd;
                y1 = fminf(fmaxf(y1, w4.x), w4.z);
                x1 = fminf(fmaxf(x1, w4.y), w4.w);
                y2 = fminf(fmaxf(y2, w4.x), w4.z);
                x2 = fminf(fmaxf(x2, w4.y), w4.w);

                if (pos < CLSMAX) {
                    g_clsKeys[bi * CLSMAX + pos] =
                        ((ull)__float_as_uint(bp) << 32) |
                        (unsigned)(0xFFFFFFFFu - (unsigned)r);
                    g_clsBox[bi * CLSMAX + pos] = make_float4(y1, x1, y2, x2);
                }
            }
        }
    }

    // ---- global barrier 1: all 80 blocks arrive, all wait ----
    __syncthreads();
    if (tid == 0) {
        __threadfence();
        atomicAdd(&g_bar1, 1);
        while (*((volatile int*)&g_bar1) < GRID) { }
    }
    __syncthreads();
    __threadfence();

    // ============ Phase 2: NMS — one block per class ========================
    const int cseg = blockIdx.x;           // 0..79
    const int c    = cseg + 1;             // class 1..80
    int cnt = min(g_clsCnt[c], CLSMAX);
    int cntK = 0;
    ull kept0 = 0ULL, kept1 = 0ULL;

    if (cnt > 0) {
        ull    myKey = 0;
        float4 myBox;
        if (tid < cnt) {
            myKey = g_clsKeys[c * CLSMAX + tid];
            myBox = g_clsBox[c * CLSMAX + tid];
            u.p2.keys[tid] = myKey;
        }
        __syncthreads();

        // Block rank-sort (descending): rank = #{keys greater}; keys unique.
        if (tid < cnt) {
            int rk = 0;
            for (int j = 0; j < cnt; j++) rk += (u.p2.keys[j] > myKey);
            u.p2.skey[rk] = myKey;
            u.p2.box[rk]  = myBox;
            u.p2.ar[rk]   = fmaxf(myBox.z - myBox.x, 0.0f) *
                            fmaxf(myBox.w - myBox.y, 0.0f);
        }
        __syncthreads();

        // Overlap mask build: one (row i, 32-wide chunk k) item per thread.
        if (tid < cnt * 4) {
            int i = tid % cnt;
            int k = tid / cnt;                 // 0..3
            float4 bi = u.p2.box[i];
            float  ia = u.p2.ar[i];
            unsigned w = 0u;
            int jend = min(i, (k + 1) * 32);
            for (int j = k * 32; j < jend; j++) {
                float4 bj = u.p2.box[j];
                float yy1 = fmaxf(bi.x, bj.x);
                float xx1 = fmaxf(bi.y, bj.y);
                float yy2 = fminf(bi.z, bj.z);
                float xx2 = fminf(bi.w, bj.w);
                float inter = fmaxf(yy2 - yy1, 0.0f) * fmaxf(xx2 - xx1, 0.0f);
                float uni   = ia + u.p2.ar[j] - inter;
                // iou > THR  <=>  uni>0 && inter > THR*max(uni,1e-12)
                if (uni > 0.0f && inter > NMS_THR * fmaxf(uni, 1e-12f))
                    w |= 1u << (j - k * 32);
            }
            ((unsigned*)&u.p2.mask[i])[k] = w;
        }
        __syncthreads();

        // Serial greedy sweep, replicated per thread (broadcast LDS.128,
        // prefetched, pure ALU). Replication is wall-clock free: all warps
        // run it concurrently; the alternative (one warp) idles the chip.
        uint4 nxt = u.p2.mask[0];
        for (int i = 0; i < cnt; i++) {
            uint4 cur = nxt;
            if (i + 1 < cnt) nxt = u.p2.mask[i + 1];
            ull lo = (ull)cur.x | ((ull)cur.y << 32);
            ull hi = (ull)cur.z | ((ull)cur.w << 32);
            bool ok = (((lo & kept0) | (hi & kept1)) == 0ULL) && (cntK < MAXI);
            if (ok) {
                if (i < 64) kept0 |= 1ULL << i;
                else        kept1 |= 1ULL << (i - 64);
                cntK++;
            }
        }

        // Reserve a compact segment, then emit kept (key, box, cls) + hist.
        if (tid == 0) s_base = atomicAdd(&g_keptTotal, cntK);
        __syncthreads();
        int base = s_base;

        if (tid < cnt) {
            int t = tid;
            bool isKept = (t < 64) ? ((kept0 >> t) & 1ULL)
                                   : ((kept1 >> (t - 64)) & 1ULL);
            if (isKept) {
                int rank;
                if (t < 64) rank = __popcll(kept0 & ((1ULL << t) - 1ULL));
                else        rank = __popcll(kept0) +
                                   __popcll(kept1 & ((1ULL << (t - 64)) - 1ULL));
                ull key = u.p2.skey[t];
                g_kKey[base + rank] = key;
                g_kBox[base + rank] = u.p2.box[t];
                g_kCls[base + rank] = c;
                float sc = __uint_as_float((unsigned)(key >> 32));
                atomicAdd(&g_hist[score_bin(sc)], 1);
            }
        }
    }

    // ---- barrier 2: last-arriving block runs phase 3 (no spin) ----
    __syncthreads();
    if (tid == 0) {
        __threadfence();
        int prev = atomicAdd(&g_bar2, 1);
        s_flag = (prev == GRID - 1);
    }
    __syncthreads();
    if (!s_flag) return;
    __threadfence();

    // ==================== Phase 3: top-100 (last block) =====================
    const int n = *((volatile int*)&g_keptTotal);

    for (int b = tid; b < 1024; b += TPB) {
        u.p3.hist[b] = g_hist[b];
        g_hist[b] = 0;                         // clear for next launch
    }
    if (tid == 0) { s_ccnt = 0; s_bstar = 0; }
    if (tid < MAXI) {
        #pragma unroll
        for (int q = 0; q < 6; q++) out[tid * 6 + q] = 0.0f;
    }
    __syncthreads();

    // Warp 0: suffix-scan 1024 bins; B = largest bin with S(B) >= MAXI.
    if (warp == 0) {
        int base = lane * 32;
        int csum = 0;
        #pragma unroll
        for (int b = 0; b < 32; b++) csum += u.p3.hist[base + b];
        int v = csum;
        #pragma unroll
        for (int off = 1; off < 32; off <<= 1) {
            int t = __shfl_down_sync(0xffffffffu, v, off);
            if (lane + off < 32) v += t;
        }
        int running = v - csum;                // suffix of higher 32-chunks
        for (int b = 31; b >= 0; b--) {
            int S = running + u.p3.hist[base + b];
            if (S >= MAXI && running < MAXI) s_bstar = base + b;
            running = S;
        }
    }
    __syncthreads();
    const int B = s_bstar;

    // Collect candidates with bin >= B from the compact list (coalesced).
    for (int s = tid; s < n; s += TPB) {
        ull key = g_kKey[s];
        float sc = __uint_as_float((unsigned)(key >> 32));
        if (score_bin(sc) >= B) {
            int pos = atomicAdd(&s_ccnt, 1);
            if (pos < CANDCAP) {
                u.p3.ckey[pos] = key;
                u.p3.cbox[pos] = g_kBox[s];    // issued now, consumed post-sync
                u.p3.ccls[pos] = g_kCls[s];
            }
        }
    }
    __syncthreads();
    int k2 = min(s_ccnt, CANDCAP);

    // Rank-select: rank = #{keys greater}; unique keys -> unique ranks.
    for (int t = tid; t < k2; t += TPB) {
        ull key = u.p3.ckey[t];
        int rank = 0;
        for (int j = 0; j < k2; j++) rank += (u.p3.ckey[j] > key);
        if (rank < MAXI) {
            float4 b4 = u.p3.cbox[t];
            out[rank * 6 + 0] = b4.x;
            out[rank * 6 + 1] = b4.y;
            out[rank * 6 + 2] = b4.z;
            out[rank * 6 + 3] = b4.w;
            out[rank * 6 + 4] = (float)u.p3.ccls[t];
            out[rank * 6 + 5] = __uint_as_float((unsigned)(key >> 32));
        }
    }

    // Reset counters for the next (graph-replayed) launch.
    __syncthreads();
    if (tid < NCLS) g_clsCnt[tid] = 0;
    if (tid == 128) g_bar1 = 0;
    if (tid == 129) g_bar2 = 0;
    if (tid == 130) g_keptTotal = 0;
}

extern "C" void kernel_launch(void* const* d_in, const int* in_sizes, int n_in,
                              void* d_out, int out_size)
{
    const float* rois   = (const float*)d_in[0];
    const float* probs  = (const float*)d_in[1];
    const float* deltas = (const float*)d_in[2];
    const float* window = (const float*)d_in[3];
    float* out = (float*)d_out;

    k_all<<<GRID, TPB>>>(rois, probs, deltas, window, out);
}

// round 16
// speedup vs baseline: 1.5008x; 1.1405x over previous
#include <cuda_runtime.h>
#include <cstdint>

#define NBOX      5000
#define NCLS      81
#define MAXI      100
#define CLSMAX    128
#define GRID      80           // one block per class; all co-resident
#define TPB       512          // 16 warps -> 1280 warps >= 1250 ROI-quads
#define KEPTMAX   (80 * MAXI)
#define CANDCAP   512
#define PRELOAD   8            // keys preloaded per thread (covers 4096)
#define MIN_CONF  0.7f
#define NMS_THR   0.3f

typedef unsigned long long ull;

// Persistent scratch. Counters zero at load; re-zeroed each launch by the
// phase-3 block -> deterministic across graph replays.
__device__ ull    g_clsKeys[NCLS * CLSMAX];
__device__ float4 g_clsBox[NCLS * CLSMAX];
__device__ int    g_clsCnt[NCLS];
__device__ ull    g_kKey[KEPTMAX];          // compact kept list
__device__ float4 g_kBox[KEPTMAX];
__device__ int    g_kCls[KEPTMAX];
__device__ int    g_keptTotal;
__device__ int    g_hist[1024];
__device__ int    g_bar1;
__device__ int    g_bar2;

__device__ __forceinline__ int score_bin(float s) {
    int b = (int)((s - MIN_CONF) * (1024.0f / 0.3f));
    return min(1023, max(0, b));
}

struct P2 {                        // phase-2 workspace: ONE class per block
    ull    keys[CLSMAX];
    ull    skey[CLSMAX];
    float4 box[CLSMAX];
    float  ar[CLSMAX];
    uint4  mask[CLSMAX];           // 128-bit overlap mask per row (lower-tri)
};
struct P3 {                        // phase-3 workspace
    int    hist[1024];
    ull    ckey[CANDCAP];
    int    cslot[CANDCAP];
};
union SmemU { P2 p2; P3 p3; };

__global__ void __launch_bounds__(TPB)
k_all(const float* __restrict__ rois,
      const float* __restrict__ probs,
      const float* __restrict__ deltas,
      const float* __restrict__ window,
      float* __restrict__ out)
{
    const int tid  = threadIdx.x;
    const int warp = tid >> 5;
    const int lane = tid & 31;
    const int gw   = blockIdx.x * (TPB / 32) + warp;   // 0..1279

    __shared__ SmemU u;
    __shared__ int s_flag, s_ccnt, s_bstar, s_base;

    // ============ Phase 1: refine — one ROI-quad per warp ==================
    const int r0 = 4 * gw;
    if (r0 < NBOX) {
        const float4 w4 = ((const float4*)window)[0];  // (wy1,wx1,wy2,wx2)

        float4 roi;
        if (lane < 4) roi = ((const float4*)rois)[r0 + lane];

        // All 12 probs loads issued upfront (independent -> high MLP).
        ull key[4];
        #pragma unroll
        for (int q = 0; q < 4; q++) {
            const float* p = probs + (size_t)(r0 + q) * NCLS;
            float v0 = p[lane];
            float v1 = p[lane + 32];
            float v2 = (lane < NCLS - 64) ? p[lane + 64] : -1.0f;
            ull k0 = ((ull)__float_as_uint(v0) << 32) | (0xFFFFFFFFu - (unsigned)lane);
            ull k1 = ((ull)__float_as_uint(v1) << 32) | (0xFFFFFFFFu - (unsigned)(lane + 32));
            ull k2 = (lane < NCLS - 64)
                   ? (((ull)__float_as_uint(v2) << 32) | (0xFFFFFFFFu - (unsigned)(lane + 64)))
                   : 0ULL;
            key[q] = max(k0, max(k1, k2));     // max prob, tie -> lower class
        }
        #pragma unroll
        for (int off = 16; off; off >>= 1) {
            #pragma unroll
            for (int q = 0; q < 4; q++) {
                ull o = __shfl_xor_sync(0xffffffffu, key[q], off);
                key[q] = max(key[q], o);
            }
        }

        if (lane < 4) {
            ull  k  = key[lane];
            float bp = __uint_as_float((unsigned)(k >> 32));
            int   bi = (int)(0xFFFFFFFFu - (unsigned)(k & 0xFFFFFFFFu));
            if (bi > 0 && bp >= MIN_CONF) {
                int r = r0 + lane;
                // Atomic first: its round-trip overlaps the deltas gather.
                int pos = atomicAdd(&g_clsCnt[bi], 1);
                float4 d4 = *(const float4*)(deltas + ((size_t)r * NCLS + bi) * 4);
                float h  = roi.z - roi.x;
                float wd = roi.w - roi.y;
                float cy = roi.x + 0.5f * h;
                float cx = roi.y + 0.5f * wd;
                cy += (d4.x * 0.1f) * h;
                cx += (d4.y * 0.1f) * wd;
                h  *= expf(d4.z * 0.2f);
                wd *= expf(d4.w * 0.2f);
                float y1 = cy - 0.5f * h;
                float x1 = cx - 0.5f * wd;
                float y2 = y1 + h;
                float x2 = x1 + wd;
                y1 = fminf(fmaxf(y1, w4.x), w4.z);
                x1 = fminf(fmaxf(x1, w4.y), w4.w);
                y2 = fminf(fmaxf(y2, w4.x), w4.z);
                x2 = fminf(fmaxf(x2, w4.y), w4.w);

                if (pos < CLSMAX) {
                    g_clsKeys[bi * CLSMAX + pos] =
                        ((ull)__float_as_uint(bp) << 32) |
                        (unsigned)(0xFFFFFFFFu - (unsigned)r);
                    g_clsBox[bi * CLSMAX + pos] = make_float4(y1, x1, y2, x2);
                }
            }
        }
    }

    // ---- global barrier 1: all 80 blocks arrive, all wait ----
    __syncthreads();
    if (tid == 0) {
        __threadfence();
        atomicAdd(&g_bar1, 1);
        while (*((volatile int*)&g_bar1) < GRID) { }
    }
    __syncthreads();
    __threadfence();

    // ============ Phase 2: NMS — one block per class ========================
    const int cseg = blockIdx.x;           // 0..79
    const int c    = cseg + 1;             // class 1..80
    int cnt = min(g_clsCnt[c], CLSMAX);
    int cntK = 0;
    ull kept0 = 0ULL, kept1 = 0ULL;

    if (cnt > 0) {
        ull    myKey = 0;
        float4 myBox;
        if (tid < cnt) {
            myKey = g_clsKeys[c * CLSMAX + tid];
            myBox = g_clsBox[c * CLSMAX + tid];
            u.p2.keys[tid] = myKey;
        }
        __syncthreads();

        // Block rank-sort (descending): rank = #{keys greater}; keys unique.
        if (tid < cnt) {
            int rk = 0;
            for (int j = 0; j < cnt; j++) rk += (u.p2.keys[j] > myKey);
            u.p2.skey[rk] = myKey;
            u.p2.box[rk]  = myBox;
            u.p2.ar[rk]   = fmaxf(myBox.z - myBox.x, 0.0f) *
                            fmaxf(myBox.w - myBox.y, 0.0f);
        }
        __syncthreads();

        // Overlap mask build: one (row i, 32-wide chunk k) item per thread.
        if (tid < cnt * 4) {
            int i = tid % cnt;
            int k = tid / cnt;                 // 0..3
            float4 bi = u.p2.box[i];
            float  ia = u.p2.ar[i];
            unsigned w = 0u;
            int jend = min(i, (k + 1) * 32);
            for (int j = k * 32; j < jend; j++) {
                float4 bj = u.p2.box[j];
                float yy1 = fmaxf(bi.x, bj.x);
                float xx1 = fmaxf(bi.y, bj.y);
                float yy2 = fminf(bi.z, bj.z);
                float xx2 = fminf(bi.w, bj.w);
                float inter = fmaxf(yy2 - yy1, 0.0f) * fmaxf(xx2 - xx1, 0.0f);
                float uni   = ia + u.p2.ar[j] - inter;
                // iou > THR  <=>  uni>0 && inter > THR*max(uni,1e-12)
                if (uni > 0.0f && inter > NMS_THR * fmaxf(uni, 1e-12f))
                    w |= 1u << (j - k * 32);
            }
            ((unsigned*)&u.p2.mask[i])[k] = w;
        }
        __syncthreads();

        // Serial greedy sweep, replicated per thread (replication is
        // wall-clock free; all warps run concurrently).
        if (cnt <= 64) {
            // FAST PATH: masks fit in 64 bits; cap cannot bind (cnt < MAXI).
            const ull* mp = (const ull*)&u.p2.mask[0];
            ull nxt = mp[0];
            for (int i = 0; i < cnt; i++) {
                ull cur = nxt;
                if (i + 1 < cnt) nxt = ((const ull*)&u.p2.mask[i + 1])[0];
                if ((cur & kept0) == 0ULL) kept0 |= 1ULL << i;
            }
            cntK = __popcll(kept0);
        } else {
            uint4 nxt = u.p2.mask[0];
            for (int i = 0; i < cnt; i++) {
                uint4 cur = nxt;
                if (i + 1 < cnt) nxt = u.p2.mask[i + 1];
                ull lo = (ull)cur.x | ((ull)cur.y << 32);
                ull hi = (ull)cur.z | ((ull)cur.w << 32);
                bool ok = (((lo & kept0) | (hi & kept1)) == 0ULL) && (cntK < MAXI);
                if (ok) {
                    if (i < 64) kept0 |= 1ULL << i;
                    else        kept1 |= 1ULL << (i - 64);
                    cntK++;
                }
            }
        }

        // Reserve a compact segment, then emit kept (key, box, cls) + hist.
        if (tid == 0) s_base = atomicAdd(&g_keptTotal, cntK);
        __syncthreads();
        int base = s_base;

        if (tid < cnt) {
            int t = tid;
            bool isKept = (t < 64) ? ((kept0 >> t) & 1ULL)
                                   : ((kept1 >> (t - 64)) & 1ULL);
            if (isKept) {
                int rank;
                if (t < 64) rank = __popcll(kept0 & ((1ULL << t) - 1ULL));
                else        rank = __popcll(kept0) +
                                   __popcll(kept1 & ((1ULL << (t - 64)) - 1ULL));
                ull key = u.p2.skey[t];
                g_kKey[base + rank] = key;
                g_kBox[base + rank] = u.p2.box[t];
                g_kCls[base + rank] = c;
                float sc = __uint_as_float((unsigned)(key >> 32));
                atomicAdd(&g_hist[score_bin(sc)], 1);
            }
        }
    }

    // ---- barrier 2: last-arriving block runs phase 3 (no spin) ----
    __syncthreads();
    if (tid == 0) {
        __threadfence();
        int prev = atomicAdd(&g_bar2, 1);
        s_flag = (prev == GRID - 1);
    }
    __syncthreads();
    if (!s_flag) return;
    __threadfence();

    // ==================== Phase 3: top-100 (last block) =====================
    const int n = *((volatile int*)&g_keptTotal);

    // Preload kept keys into registers BEFORE the scan (overlaps hist RT +
    // scan compute). Covers PRELOAD*TPB = 4096 entries; fallback below.
    ull pk[PRELOAD];
    #pragma unroll
    for (int q = 0; q < PRELOAD; q++) {
        int s = tid + q * TPB;
        pk[q] = (s < n) ? g_kKey[s] : 0ULL;
    }

    for (int b = tid; b < 1024; b += TPB) {
        u.p3.hist[b] = g_hist[b];
        g_hist[b] = 0;                         // clear for next launch
    }
    if (tid == 0) { s_ccnt = 0; s_bstar = 0; }
    if (tid < MAXI) {
        #pragma unroll
        for (int q = 0; q < 6; q++) out[tid * 6 + q] = 0.0f;
    }
    __syncthreads();

    // Warp 0: suffix-scan 1024 bins; B = largest bin with S(B) >= MAXI.
    if (warp == 0) {
        int base = lane * 32;
        int csum = 0;
        #pragma unroll
        for (int b = 0; b < 32; b++) csum += u.p3.hist[base + b];
        int v = csum;
        #pragma unroll
        for (int off = 1; off < 32; off <<= 1) {
            int t = __shfl_down_sync(0xffffffffu, v, off);
            if (lane + off < 32) v += t;
        }
        int running = v - csum;                // suffix of higher 32-chunks
        for (int b = 31; b >= 0; b--) {
            int S = running + u.p3.hist[base + b];
            if (S >= MAXI && running < MAXI) s_bstar = base + b;
            running = S;
        }
    }
    __syncthreads();
    const int B = s_bstar;

    // Filter from registers (no post-scan key RT); store (key, slot).
    #pragma unroll
    for (int q = 0; q < PRELOAD; q++) {
        int s = tid + q * TPB;
        if (s < n) {
            float sc = __uint_as_float((unsigned)(pk[q] >> 32));
            if (score_bin(sc) >= B) {
                int pos = atomicAdd(&s_ccnt, 1);
                if (pos < CANDCAP) {
                    u.p3.ckey[pos]  = pk[q];
                    u.p3.cslot[pos] = s;
                }
            }
        }
    }
    // Fallback for n > PRELOAD*TPB (never in practice; correctness guard).
    for (int s = tid + PRELOAD * TPB; s < n; s += TPB) {
        ull key = g_kKey[s];
        float sc = __uint_as_float((unsigned)(key >> 32));
        if (score_bin(sc) >= B) {
            int pos = atomicAdd(&s_ccnt, 1);
            if (pos < CANDCAP) {
                u.p3.ckey[pos]  = key;
                u.p3.cslot[pos] = s;
            }
        }
    }
    __syncthreads();
    int k2 = min(s_ccnt, CANDCAP);

    // Rank-select: thread t owns candidate t. Box/cls loads are issued
    // FIRST so their round-trip hides under the rank compute loop.
    if (tid < k2) {
        int    slot = u.p3.cslot[tid];
        float4 b4   = g_kBox[slot];            // in flight during rank loop
        int    cls  = g_kCls[slot];
        ull    key  = u.p3.ckey[tid];
        int rank = 0;
        for (int j = 0; j < k2; j++) rank += (u.p3.ckey[j] > key);
        if (rank < MAXI) {
            out[rank * 6 + 0] = b4.x;
            out[rank * 6 + 1] = b4.y;
            out[rank * 6 + 2] = b4.z;
            out[rank * 6 + 3] = b4.w;
            out[rank * 6 + 4] = (float)cls;
            out[rank * 6 + 5] = __uint_as_float((unsigned)(key >> 32));
        }
    }

    // Reset counters for the next (graph-replayed) launch.
    __syncthreads();
    if (tid < NCLS) g_clsCnt[tid] = 0;
    if (tid == 128) g_bar1 = 0;
    if (tid == 129) g_bar2 = 0;
    if (tid == 130) g_keptTotal = 0;
}

extern "C" void kernel_launch(void* const* d_in, const int* in_sizes, int n_in,
                              void* d_out, int out_size)
{
    const float* rois   = (const float*)d_in[0];
    const float* probs  = (const float*)d_in[1];
    const float* deltas = (const float*)d_in[2];
    const float* window = (const float*)d_in[3];
    float* out = (float*)d_out;

    k_all<<<GRID, TPB>>>(rois, probs, deltas, window, out);
}